// round 7
// baseline (speedup 1.0000x reference)
#include <cuda_runtime.h>

// Trilinear spatial-transformer sampler, degenerate depth axis.
// Output (1,64,64,32). Grid point (oy,ox,k) contributes only when its
// transformed z lands in [31,33) (image slab at depth 32 of the padded
// 65-deep volume). z is linear in k -> analytic active-k window.
//
// R7: 4 independent warps per pixel (16384 warps), own k-quarter each
//     (as R6), but phase 2 now processes 4 entries per iteration:
//     warp = 4 groups of 8 lanes, group g takes entry e+g, each lane
//     loads float4 of channels (8 lanes x 16B = same 128B corner line).
//     Per 4 entries: 2 LDS.128 + 4 LDG.128 + 16 FMA  (vs 8 LDS + 16 LDG
//     + 16 FMA before) -- phase-2 instructions halved, MLP=4 per lane.
//     Entries padded to a multiple of 4 with zero-weight entries.
//     Cross-group sum via 8 shuffles.
//
// Faithful semantics: trunc-toward-zero int casts, clip-then-weight,
// reference's x/y swap (weight fx[i] pairs with the row index ys[i]).

#define FULL 0xffffffffu
#define MAX_Q 20   // ceil(65/4)=17, rounded up to multiple of 4

__global__ __launch_bounds__(256) void stn_kernel(
    const float* __restrict__ img,   // (128,128,32) f32
    const float* __restrict__ T,     // 12 floats, row-major 3x4
    float* __restrict__ out)         // (64,64,32) f32
{
    // entry = 8 words: [base4, dx4, dy4, dxdy4, w00, w01, w10, w11]
    // (offsets in float4 units)
    __shared__ float sent[2][4][MAX_Q][8];
    __shared__ float spart[2][4][32];

    int warp = threadIdx.x >> 5;
    int lane = threadIdx.x & 31;
    int pg   = warp >> 2;                  // pixel slot in block (0..1)
    int wsub = warp & 3;                   // sub-warp within pixel group
    int pix  = blockIdx.x * 2 + pg;        // 0..4095
    int ox   = pix & 63;
    int oy   = (pix >> 6) & 63;

    float xg = fmaf((float)ox, 2.0f / 63.0f, -1.0f);
    float yg = fmaf((float)oy, 2.0f / 63.0f, -1.0f);

    const float4* T4 = (const float4*)T;
    float4 r0 = __ldg(T4 + 0);   // t0 t1 t2 t3
    float4 r1 = __ldg(T4 + 1);   // t4 t5 t6 t7
    float4 r2 = __ldg(T4 + 2);   // t8 t9 t10 t11

    // per-pixel base of each transformed coordinate (zg term added per-k)
    float bx = fmaf(r0.x, xg, fmaf(r0.y, yg, r0.w));
    float by = fmaf(r1.x, xg, fmaf(r1.y, yg, r1.w));
    float bz = fmaf(r2.x, xg, fmaf(r2.y, yg, r2.w));
    float t2c = r0.z, t6c = r1.z, t10c = r2.z;

    // Analytic active-k window: z(k) = C + D*k, want z in [31,33).
    float C = 32.5f * (bz + 1.0f - t10c);
    float D = t10c * (65.0f / 64.0f);

    int kLo = 0, kHi = 64;
    if (fabsf(D) > 1e-6f) {
        float invD = __frcp_rn(D);
        float k1 = (31.0f - C) * invD;
        float k2 = (33.0f - C) * invD;
        float lo = fminf(k1, k2), hi = fmaxf(k1, k2);
        lo = fminf(fmaxf(lo, -4.0f), 68.0f);
        hi = fminf(fmaxf(hi, -4.0f), 68.0f);
        kLo = max(0,  (int)floorf(lo) - 2);
        kHi = min(64, (int)ceilf(hi)  + 2);
    } else {
        if (C < 29.0f || C > 35.0f) { kHi = -1; }  // empty window
    }

    // ---------------- Phase 1: own k-quarter, single ballot chunk --------
    int len  = kHi - kLo + 1;            // 0..65
    int q    = (len + 3) >> 2;           // 0..17, always <= 32
    int myLo = kLo + wsub * q;
    int k    = myLo + lane;

    bool act = false;
    int  base = 0, dx = 0, dy = 0;
    float w00 = 0.f, w01 = 0.f, w10 = 0.f, w11 = 0.f;

    if (lane < q && k <= kHi && k <= 64) {
        float zg = fmaf((float)k, 2.0f / 64.0f, -1.0f);
        float sz = fmaf(t10c, zg, bz);
        float z  = 0.5f * (sz + 1.0f) * 65.0f;
        int zt = (int)z;                       // trunc toward zero
        if (zt == 31 || zt == 32) {
            // z0=clip(zt)=32 pairs with fz0 = 33-z (zt==32)
            // z1=clip(zt+1)=32 pairs with fz1 = z-31 (zt==31)
            float zw = (zt == 32) ? (33.0f - z) : (z - 31.0f);

            float sx = fmaf(t2c, zg, bx);
            float sy = fmaf(t6c, zg, by);
            float x = 0.5f * (sx + 1.0f) * 128.0f;
            float y = 0.5f * (sy + 1.0f) * 128.0f;

            int xi = (int)x;                   // trunc
            int yi = (int)y;
            int x0 = min(max(xi,     0), 127);
            int x1 = min(max(xi + 1, 0), 127);
            int y0 = min(max(yi,     0), 127);
            int y1 = min(max(yi + 1, 0), 127);

            // weights from CLIPPED corner coords (faithful to reference)
            float fx0 = (float)x1 - x;
            float fx1 = x - (float)x0;
            float fy0 = (float)y1 - y;
            float fy1 = y - (float)y0;

            // x/y swap: fx pairs with row (y) index, fy with col (x)
            w00 = zw * fx0 * fy0;   // (y0, x0)
            w01 = zw * fx0 * fy1;   // (y0, x1)
            w10 = zw * fx1 * fy0;   // (y1, x0)
            w11 = zw * fx1 * fy1;   // (y1, x1)

            base = ((y0 << 7) + x0) << 3;      // float4 offset of (y0,x0)
            dx   = (x1 - x0) << 3;             // 0 or 8
            dy   = (y1 - y0) << 10;            // 0 or 1024
            act  = true;
        }
    }

    float (*ent)[8] = sent[pg][wsub];
    unsigned m = __ballot_sync(FULL, act);
    int cnt = __popc(m);
    if (act) {
        float* e = ent[__popc(m & ((1u << lane) - 1u))];
        float4 h; h.x = __int_as_float(base);
                  h.y = __int_as_float(dx);
                  h.z = __int_as_float(dy);
                  h.w = __int_as_float(dx + dy);
        float4 w; w.x = w00; w.y = w01; w.z = w10; w.w = w11;
        *(float4*)&e[0] = h;
        *(float4*)&e[4] = w;
    }
    // zero-pad entries up to the next multiple of 4 (w=0 => no contribution)
    int cnt4 = (cnt + 3) & ~3;
    if (lane >= cnt && lane < cnt4) {
        float4 zv; zv.x = zv.y = zv.z = zv.w = 0.0f;
        *(float4*)&ent[lane][0] = zv;
        *(float4*)&ent[lane][4] = zv;
    }

    __syncwarp();

    // ------------ Phase 2: 4 entries/iter, 8-lane groups, float4 ---------
    int g  = lane >> 3;                  // entry group 0..3
    int cg = lane & 7;                   // float4 channel group
    const float4* imgv = (const float4*)img + cg;

    float4 acc; acc.x = acc.y = acc.z = acc.w = 0.0f;

    for (int e = g; e < cnt4; e += 4) {
        float4 hdr = *(const float4*)&ent[e][0];   // LDS.128, 8-lane bcast
        float4 w   = *(const float4*)&ent[e][4];   // LDS.128, 8-lane bcast
        int b    = __float_as_int(hdr.x);
        int ddx  = __float_as_int(hdr.y);
        int ddy  = __float_as_int(hdr.z);
        int ddxy = __float_as_int(hdr.w);

        float4 v00 = __ldg(imgv + b);
        float4 v01 = __ldg(imgv + b + ddx);
        float4 v10 = __ldg(imgv + b + ddy);
        float4 v11 = __ldg(imgv + b + ddxy);

        acc.x = fmaf(w.x, v00.x, fmaf(w.y, v01.x, fmaf(w.z, v10.x, fmaf(w.w, v11.x, acc.x))));
        acc.y = fmaf(w.x, v00.y, fmaf(w.y, v01.y, fmaf(w.z, v10.y, fmaf(w.w, v11.y, acc.y))));
        acc.z = fmaf(w.x, v00.z, fmaf(w.y, v01.z, fmaf(w.z, v10.z, fmaf(w.w, v11.z, acc.z))));
        acc.w = fmaf(w.x, v00.w, fmaf(w.y, v01.w, fmaf(w.z, v10.w, fmaf(w.w, v11.w, acc.w))));
    }

    // sum across the 4 entry-groups (lanes with equal cg)
    acc.x += __shfl_xor_sync(FULL, acc.x, 16);
    acc.y += __shfl_xor_sync(FULL, acc.y, 16);
    acc.z += __shfl_xor_sync(FULL, acc.z, 16);
    acc.w += __shfl_xor_sync(FULL, acc.w, 16);
    acc.x += __shfl_xor_sync(FULL, acc.x, 8);
    acc.y += __shfl_xor_sync(FULL, acc.y, 8);
    acc.z += __shfl_xor_sync(FULL, acc.z, 8);
    acc.w += __shfl_xor_sync(FULL, acc.w, 8);

    if (lane < 8) {
        ((float4*)spart[pg][wsub])[cg] = acc;      // STS.128
    }
    __syncthreads();

    if (wsub == 0) {
        float r = (spart[pg][0][lane] + spart[pg][1][lane])
                + (spart[pg][2][lane] + spart[pg][3][lane]);
        out[(pix << 5) + lane] = r;
    }
}

extern "C" void kernel_launch(void* const* d_in, const int* in_sizes, int n_in,
                              void* d_out, int out_size)
{
    const float* img = (const float*)d_in[0];   // (1,128,128,32) f32
    const float* T   = (const float*)d_in[1];   // (1,12) f32
    float* out       = (float*)d_out;           // (1,64,64,32) f32

    // 4 warps per pixel: 4096 pixels * 4 = 16384 warps = 2048 blocks x 256
    stn_kernel<<<2048, 256>>>(img, T, out);
}

// round 8
// speedup vs baseline: 1.0258x; 1.0258x over previous
#include <cuda_runtime.h>

// Trilinear spatial-transformer sampler, degenerate depth axis.
// Output (1,64,64,32). Grid point (oy,ox,k) contributes only when its
// transformed z lands in [31,33) (image slab at depth 32 of the padded
// 65-deep volume). z is linear in k -> analytic active-k window.
//
// R8 = R6 structure + surgical instruction cuts:
//   - entry carries 4 precomputed gather offsets (o00..o11) instead of
//     base/dx/dy (3 adds moved from phase-2 serial path to warp-parallel
//     phase 1)
//   - entries padded to even count; phase 2 explicitly unrolled by 2
//     entries: 4 LDS.128 + 8 batched LDG + 8 FMA, 8 accumulators (MLP 8)
//   - 128-thread blocks, 1 pixel/block (cheaper barrier, finer sched)
//
// Faithful semantics: trunc-toward-zero int casts, clip-then-weight,
// reference's x/y swap (weight fx[i] pairs with the row index ys[i]).

#define FULL 0xffffffffu
#define MAX_Q2 18   // ceil(65/4)=17 rounded up to even

__global__ __launch_bounds__(128) void stn_kernel(
    const float* __restrict__ img,   // (128,128,32) f32
    const float* __restrict__ T,     // 12 floats, row-major 3x4
    float* __restrict__ out)         // (64,64,32) f32
{
    // entry = 8 words: [o00, o01, o10, o11, w00, w01, w10, w11]
    __shared__ float sent[4][MAX_Q2][8];
    __shared__ float spart[4][32];

    int wsub = threadIdx.x >> 5;           // warp within pixel (0..3)
    int lane = threadIdx.x & 31;
    int pix  = blockIdx.x;                 // 0..4095
    int ox   = pix & 63;
    int oy   = (pix >> 6) & 63;

    float xg = fmaf((float)ox, 2.0f / 63.0f, -1.0f);
    float yg = fmaf((float)oy, 2.0f / 63.0f, -1.0f);

    const float4* T4 = (const float4*)T;
    float4 r0 = __ldg(T4 + 0);   // t0 t1 t2 t3
    float4 r1 = __ldg(T4 + 1);   // t4 t5 t6 t7
    float4 r2 = __ldg(T4 + 2);   // t8 t9 t10 t11

    // per-pixel base of each transformed coordinate (zg term added per-k)
    float bx = fmaf(r0.x, xg, fmaf(r0.y, yg, r0.w));
    float by = fmaf(r1.x, xg, fmaf(r1.y, yg, r1.w));
    float bz = fmaf(r2.x, xg, fmaf(r2.y, yg, r2.w));
    float t2c = r0.z, t6c = r1.z, t10c = r2.z;

    // Analytic active-k window: z(k) = C + D*k, want z in [31,33).
    float C = 32.5f * (bz + 1.0f - t10c);
    float D = t10c * (65.0f / 64.0f);

    int kLo = 0, kHi = 64;
    if (fabsf(D) > 1e-6f) {
        float invD = __frcp_rn(D);
        float k1 = (31.0f - C) * invD;
        float k2 = (33.0f - C) * invD;
        float lo = fminf(k1, k2), hi = fmaxf(k1, k2);
        lo = fminf(fmaxf(lo, -4.0f), 68.0f);
        hi = fminf(fmaxf(hi, -4.0f), 68.0f);
        kLo = max(0,  (int)floorf(lo) - 2);
        kHi = min(64, (int)ceilf(hi)  + 2);
    } else {
        if (C < 29.0f || C > 35.0f) { kHi = -1; }  // empty window
    }

    // ---------------- Phase 1: own k-quarter, single ballot chunk --------
    int len  = kHi - kLo + 1;            // 0..65
    int q    = (len + 3) >> 2;           // 0..17, always <= 32
    int myLo = kLo + wsub * q;
    int k    = myLo + lane;

    bool act = false;
    int  o00 = 0, o01 = 0, o10 = 0, o11 = 0;
    float w00 = 0.f, w01 = 0.f, w10 = 0.f, w11 = 0.f;

    if (lane < q && k <= kHi && k <= 64) {
        float zg = fmaf((float)k, 2.0f / 64.0f, -1.0f);
        float sz = fmaf(t10c, zg, bz);
        float z  = 0.5f * (sz + 1.0f) * 65.0f;
        int zt = (int)z;                       // trunc toward zero
        if (zt == 31 || zt == 32) {
            // z0=clip(zt)=32 pairs with fz0 = 33-z (zt==32)
            // z1=clip(zt+1)=32 pairs with fz1 = z-31 (zt==31)
            float zw = (zt == 32) ? (33.0f - z) : (z - 31.0f);

            float sx = fmaf(t2c, zg, bx);
            float sy = fmaf(t6c, zg, by);
            float x = 0.5f * (sx + 1.0f) * 128.0f;
            float y = 0.5f * (sy + 1.0f) * 128.0f;

            int xi = (int)x;                   // trunc
            int yi = (int)y;
            int x0 = min(max(xi,     0), 127);
            int x1 = min(max(xi + 1, 0), 127);
            int y0 = min(max(yi,     0), 127);
            int y1 = min(max(yi + 1, 0), 127);

            // weights from CLIPPED corner coords (faithful to reference)
            float fx0 = (float)x1 - x;
            float fx1 = x - (float)x0;
            float fy0 = (float)y1 - y;
            float fy1 = y - (float)y0;

            // x/y swap: fx pairs with row (y) index, fy with col (x)
            w00 = zw * fx0 * fy0;   // (y0, x0)
            w01 = zw * fx0 * fy1;   // (y0, x1)
            w10 = zw * fx1 * fy0;   // (y1, x0)
            w11 = zw * fx1 * fy1;   // (y1, x1)

            int base = ((y0 << 7) + x0) << 5;  // float offset of (y0,x0,c0)
            int dx   = (x1 - x0) << 5;         // 0 or 32
            int dy   = (y1 - y0) << 12;        // 0 or 4096
            o00 = base;
            o01 = base + dx;
            o10 = base + dy;
            o11 = base + dx + dy;
            act = true;
        }
    }

    float (*ent)[8] = sent[wsub];
    unsigned m = __ballot_sync(FULL, act);
    int cnt = __popc(m);
    if (act) {
        float* e = ent[__popc(m & ((1u << lane) - 1u))];
        float4 h; h.x = __int_as_float(o00);
                  h.y = __int_as_float(o01);
                  h.z = __int_as_float(o10);
                  h.w = __int_as_float(o11);
        float4 w; w.x = w00; w.y = w01; w.z = w10; w.w = w11;
        *(float4*)&e[0] = h;
        *(float4*)&e[4] = w;
    }
    // pad to even count with a zero-weight dummy (offset 0 = valid addr)
    if ((cnt & 1) && lane == cnt) {
        float4 zv; zv.x = zv.y = zv.z = zv.w = 0.0f;
        *(float4*)&ent[cnt][0] = zv;
        *(float4*)&ent[cnt][4] = zv;
    }
    int cnt2 = (cnt + 1) & ~1;

    __syncwarp();

    // ------------- Phase 2: 2 entries/iter, lane = channel ---------------
    const float* imgc = img + lane;
    float a0 = 0.f, a1 = 0.f, a2 = 0.f, a3 = 0.f;
    float b0 = 0.f, b1 = 0.f, b2 = 0.f, b3 = 0.f;

    for (int e = 0; e < cnt2; e += 2) {
        float4 hA = *(const float4*)&ent[e][0];      // LDS.128 broadcast
        float4 wA = *(const float4*)&ent[e][4];
        float4 hB = *(const float4*)&ent[e + 1][0];
        float4 wB = *(const float4*)&ent[e + 1][4];

        float vA0 = __ldg(imgc + __float_as_int(hA.x));
        float vA1 = __ldg(imgc + __float_as_int(hA.y));
        float vA2 = __ldg(imgc + __float_as_int(hA.z));
        float vA3 = __ldg(imgc + __float_as_int(hA.w));
        float vB0 = __ldg(imgc + __float_as_int(hB.x));
        float vB1 = __ldg(imgc + __float_as_int(hB.y));
        float vB2 = __ldg(imgc + __float_as_int(hB.z));
        float vB3 = __ldg(imgc + __float_as_int(hB.w));

        a0 = fmaf(wA.x, vA0, a0);
        a1 = fmaf(wA.y, vA1, a1);
        a2 = fmaf(wA.z, vA2, a2);
        a3 = fmaf(wA.w, vA3, a3);
        b0 = fmaf(wB.x, vB0, b0);
        b1 = fmaf(wB.y, vB1, b1);
        b2 = fmaf(wB.z, vB2, b2);
        b3 = fmaf(wB.w, vB3, b3);
    }

    spart[wsub][lane] = ((a0 + a1) + (a2 + a3)) + ((b0 + b1) + (b2 + b3));
    __syncthreads();

    if (wsub == 0) {
        float r = (spart[0][lane] + spart[1][lane])
                + (spart[2][lane] + spart[3][lane]);
        out[(pix << 5) + lane] = r;
    }
}

extern "C" void kernel_launch(void* const* d_in, const int* in_sizes, int n_in,
                              void* d_out, int out_size)
{
    const float* img = (const float*)d_in[0];   // (1,128,128,32) f32
    const float* T   = (const float*)d_in[1];   // (1,12) f32
    float* out       = (float*)d_out;           // (1,64,64,32) f32

    // 1 pixel per 128-thread block, 4 warps/pixel: 4096 blocks
    stn_kernel<<<4096, 128>>>(img, T, out);
}